// round 14
// baseline (speedup 1.0000x reference)
#include <cuda_runtime.h>
#include <cuda_bf16.h>
#include <math.h>
#include <stdint.h>

// Problem constants (fixed shapes for this problem)
#define BB   8
#define LL   4096
#define DD   512
#define HH   8
#define EE   64
#define UMAX 48
#define NROWS (BB*LL)          // 32768
#define NBH   (BB*HH)          // 64
#define NSPLIT 8               // K-splits for ctx GEMM

// ---------------- scratch (static device allocations, allowed) ----------------
__device__ float g_Q[(size_t)NROWS*DD];                  // 64 MB, natural (b,l,d)
__device__ float g_K[(size_t)NROWS*DD];                  // 64 MB
__device__ float g_V[(size_t)NROWS*DD];                  // 64 MB
__device__ float g_M[(size_t)NBH*LL];                    // 1 MB
__device__ int   g_top[NBH*UMAX];                        // top-u indices per (b,h)
__device__ float g_S[(size_t)NBH*UMAX*LL];               // 48 MB: exp(scores), unnormalized
__device__ float g_rowsum[NBH*UMAX];                     // per-(bh,q) sum of exp
__device__ float g_ctxP[(size_t)NSPLIT*NBH*UMAX*EE];     // 6 MB partial ctx
__device__ float g_vsum[BB*DD];                          // V column sums per batch
__device__ float g_base[BB*DD];                          // base output row per batch

// bf16 split operands for tensor-core projections
__device__ __nv_bfloat16 g_Ah[(size_t)3*NROWS*DD];       // 96 MB
__device__ __nv_bfloat16 g_Al[(size_t)3*NROWS*DD];       // 96 MB
__device__ __nv_bfloat16 g_Wth[(size_t)3*DD*DD];         // W^T hi  [n][k]
__device__ __nv_bfloat16 g_Wtl[(size_t)3*DD*DD];         // W^T lo  [n][k]

// ================= helpers =================
__device__ __forceinline__ uint32_t smem_u32(const void* p) {
    uint32_t a;
    asm("{ .reg .u64 t; cvta.to.shared.u64 t, %1; cvt.u32.u64 %0, t; }" : "=r"(a) : "l"(p));
    return a;
}

// FMA-pipe exp (no MUFU): x*log2e, magic-number round, degree-6 2^f Taylor,
// exponent splice by integer add. ~1e-7 rel err. Clamped to [-87, 80].
__device__ __forceinline__ float fexp(float x) {
    x = fmaxf(fminf(x, 80.0f), -87.0f);
    float t = x * 1.4426950408889634f;
    float r = t + 12582912.0f;                   // 1.5 * 2^23 magic RN
    int   k = __float_as_int(r) - 0x4B400000;    // round(t) as integer
    float f = t - (r - 12582912.0f);             // t - round(t), in [-0.5, 0.5]
    float p = 1.5402387e-4f;
    p = fmaf(p, f, 1.3333558e-3f);
    p = fmaf(p, f, 9.6181291e-3f);
    p = fmaf(p, f, 5.5504109e-2f);
    p = fmaf(p, f, 2.4022651e-1f);
    p = fmaf(p, f, 6.9314718e-1f);
    p = fmaf(p, f, 1.0f);
    return __int_as_float(__float_as_int(p) + (k << 23));
}

#define CP_ASYNC16(dst, src) \
    asm volatile("cp.async.ca.shared.global [%0], [%1], 16;" :: "r"(dst), "l"(src) : "memory")
#define CP_COMMIT() asm volatile("cp.async.commit_group;" ::: "memory")
#define CP_WAIT2()  asm volatile("cp.async.wait_group 2;" ::: "memory")

#define LDM4(r, addr) \
    asm volatile("ldmatrix.sync.aligned.m8n8.x4.shared.b16 {%0,%1,%2,%3}, [%4];" \
        : "=r"((r)[0]), "=r"((r)[1]), "=r"((r)[2]), "=r"((r)[3]) : "r"(addr))

#define MMA16816(d, a, b0, b1) \
    asm volatile("mma.sync.aligned.m16n8k16.row.col.f32.bf16.bf16.f32 " \
        "{%0,%1,%2,%3}, {%4,%5,%6,%7}, {%8,%9}, {%0,%1,%2,%3};" \
        : "+f"((d)[0]), "+f"((d)[1]), "+f"((d)[2]), "+f"((d)[3]) \
        : "r"((a)[0]), "r"((a)[1]), "r"((a)[2]), "r"((a)[3]), "r"(b0), "r"(b1))

// ---------------- split kernels ----------------
__global__ void __launch_bounds__(256)
splitA_kernel(const float* __restrict__ q, const float* __restrict__ k, const float* __restrict__ v)
{
    int z = blockIdx.y;
    const float* src = (z == 0) ? q : ((z == 1) ? k : v);
    size_t i4 = (size_t)blockIdx.x * 256 + threadIdx.x;
    float4 a = ((const float4*)src)[i4];
    __nv_bfloat16 hx = __float2bfloat16_rn(a.x);
    __nv_bfloat16 hy = __float2bfloat16_rn(a.y);
    __nv_bfloat16 hz = __float2bfloat16_rn(a.z);
    __nv_bfloat16 hw = __float2bfloat16_rn(a.w);
    __nv_bfloat16 lx = __float2bfloat16_rn(a.x - __bfloat162float(hx));
    __nv_bfloat16 ly = __float2bfloat16_rn(a.y - __bfloat162float(hy));
    __nv_bfloat16 lz = __float2bfloat16_rn(a.z - __bfloat162float(hz));
    __nv_bfloat16 lw = __float2bfloat16_rn(a.w - __bfloat162float(hw));
    __nv_bfloat162* dh = (__nv_bfloat162*)(g_Ah + (size_t)z * NROWS * DD);
    __nv_bfloat162* dl = (__nv_bfloat162*)(g_Al + (size_t)z * NROWS * DD);
    dh[i4 * 2]     = __halves2bfloat162(hx, hy);
    dh[i4 * 2 + 1] = __halves2bfloat162(hz, hw);
    dl[i4 * 2]     = __halves2bfloat162(lx, ly);
    dl[i4 * 2 + 1] = __halves2bfloat162(lz, lw);
}

__global__ void splitW_kernel(const float* __restrict__ WQ, const float* __restrict__ WK,
                              const float* __restrict__ WV)
{
    __shared__ float t[32][33];
    int z = blockIdx.z;
    const float* W = (z == 0) ? WQ : ((z == 1) ? WK : WV);
    int k = blockIdx.y * 32 + threadIdx.y;
    int n = blockIdx.x * 32 + threadIdx.x;
    t[threadIdx.y][threadIdx.x] = W[(size_t)k * DD + n];
    __syncthreads();
    int n2 = blockIdx.x * 32 + threadIdx.y;
    int k2 = blockIdx.y * 32 + threadIdx.x;
    float v = t[threadIdx.x][threadIdx.y];
    __nv_bfloat16 h = __float2bfloat16_rn(v);
    __nv_bfloat16 l = __float2bfloat16_rn(v - __bfloat162float(h));
    g_Wth[(size_t)z * DD * DD + (size_t)n2 * DD + k2] = h;
    g_Wtl[(size_t)z * DD * DD + (size_t)n2 * DD + k2] = l;
}

// ---------------- HMMA projection GEMM (round-6 best config) ----------------
#define NSTAGE  4
#define STAGE_B 16384        // A: 128*64B = 8192 ; W: 128*64B = 8192
#define GEMM_SMEM (NSTAGE*STAGE_B)   // 65536
#define KITER 48             // 1536 / 32

__global__ void __launch_bounds__(256, 2)
hmma_gemm_kernel(float* __restrict__ outQ, float* __restrict__ outK, float* __restrict__ outV)
{
    extern __shared__ char smem[];
    const uint32_t sb = smem_u32(smem);
    const int tid = threadIdx.x;
    const int z = blockIdx.z;
    const int mBase = blockIdx.y * 128;
    const int nBase = blockIdx.x * 128;

    const __nv_bfloat16* __restrict__ Ah = g_Ah + (size_t)z * NROWS * DD;
    const __nv_bfloat16* __restrict__ Al = g_Al + (size_t)z * NROWS * DD;
    const __nv_bfloat16* __restrict__ Wh = g_Wth + (size_t)z * DD * DD;
    const __nv_bfloat16* __restrict__ Wl = g_Wtl + (size_t)z * DD * DD;
    float* __restrict__ out = (z == 0) ? outQ : ((z == 1) ? outK : outV);

    const int r0 = tid >> 2, c0 = tid & 3;
    const int r1 = (tid + 256) >> 2, c1 = tid & 3;
    const uint32_t aDst0 = sb + r0 * 64 + ((c0 ^ ((r0 >> 1) & 3)) * 16);
    const uint32_t aDst1 = sb + r1 * 64 + ((c1 ^ ((r1 >> 1) & 3)) * 16);
    const uint32_t wDst0 = aDst0 + 8192;
    const uint32_t wDst1 = aDst1 + 8192;
    const size_t aSrc0 = (size_t)(mBase + r0) * DD + c0 * 8;
    const size_t aSrc1 = (size_t)(mBase + r1) * DD + c1 * 8;
    const size_t wSrc0 = (size_t)(nBase + r0) * DD + c0 * 8;
    const size_t wSrc1 = (size_t)(nBase + r1) * DD + c1 * 8;

    const int wid = tid >> 5, lane = tid & 31;
    const int warp_m = (wid >> 1) * 32;
    const int warp_n = (wid & 1) * 64;
    const int lrow = lane & 15;
    const int lkc = lane >> 4;
    const int xr = (lrow >> 1) & 3;
    uint32_t aAddr[2], wAddr[4];
#pragma unroll
    for (int mf = 0; mf < 2; mf++) aAddr[mf] = sb + (warp_m + mf * 16 + lrow) * 64;
#pragma unroll
    for (int nf = 0; nf < 4; nf++) wAddr[nf] = sb + 8192 + (warp_n + nf * 16 + lrow) * 64;

    float acc[2][8][4];
#pragma unroll
    for (int mf = 0; mf < 2; mf++)
#pragma unroll
        for (int ns = 0; ns < 8; ns++)
#pragma unroll
            for (int e = 0; e < 4; e++) acc[mf][ns][e] = 0.f;

#pragma unroll
    for (int s = 0; s < NSTAGE - 1; s++) {
        int kt = s * 32;
        int r = kt >> 9, kk = kt & 511;
        const __nv_bfloat16* As_ = (r == 1) ? Al : Ah;
        const __nv_bfloat16* Ws_ = (r == 2) ? Wl : Wh;
        uint32_t so = (uint32_t)s * STAGE_B;
        CP_ASYNC16(aDst0 + so, As_ + aSrc0 + kk);
        CP_ASYNC16(aDst1 + so, As_ + aSrc1 + kk);
        CP_ASYNC16(wDst0 + so, Ws_ + wSrc0 + kk);
        CP_ASYNC16(wDst1 + so, Ws_ + wSrc1 + kk);
        CP_COMMIT();
    }

    for (int it = 0; it < KITER; it++) {
        CP_WAIT2();
        __syncthreads();
        int nit = it + NSTAGE - 1;
        if (nit < KITER) {
            int kt = nit * 32;
            int r = kt >> 9, kk = kt & 511;
            const __nv_bfloat16* As_ = (r == 1) ? Al : Ah;
            const __nv_bfloat16* Ws_ = (r == 2) ? Wl : Wh;
            uint32_t so2 = (uint32_t)(nit & 3) * STAGE_B;
            CP_ASYNC16(aDst0 + so2, As_ + aSrc0 + kk);
            CP_ASYNC16(aDst1 + so2, As_ + aSrc1 + kk);
            CP_ASYNC16(wDst0 + so2, Ws_ + wSrc0 + kk);
            CP_ASYNC16(wDst1 + so2, Ws_ + wSrc1 + kk);
        }
        CP_COMMIT();

        uint32_t so = (uint32_t)(it & 3) * STAGE_B;
#pragma unroll
        for (int ks = 0; ks < 2; ks++) {
            uint32_t csOff = (uint32_t)((((ks << 1) | lkc) ^ xr) * 16) + so;
            uint32_t a[2][4], b[4][4];
#pragma unroll
            for (int mf = 0; mf < 2; mf++) LDM4(a[mf], aAddr[mf] + csOff);
#pragma unroll
            for (int nf = 0; nf < 4; nf++) LDM4(b[nf], wAddr[nf] + csOff);
#pragma unroll
            for (int mf = 0; mf < 2; mf++)
#pragma unroll
                for (int nf = 0; nf < 4; nf++) {
                    MMA16816(acc[mf][nf * 2],     a[mf], b[nf][0], b[nf][2]);
                    MMA16816(acc[mf][nf * 2 + 1], a[mf], b[nf][1], b[nf][3]);
                }
        }
    }

    const int tg = lane >> 2;
    const int tc = (lane & 3) * 2;
#pragma unroll
    for (int mf = 0; mf < 2; mf++) {
        int row0 = mBase + warp_m + mf * 16 + tg;
#pragma unroll
        for (int nf = 0; nf < 4; nf++)
#pragma unroll
            for (int sub = 0; sub < 2; sub++) {
                float* f = acc[mf][nf * 2 + sub];
                int col = nBase + warp_n + nf * 16 + sub * 8 + tc;
                *(float2*)&out[(size_t)row0 * DD + col]       = make_float2(f[0], f[1]);
                *(float2*)&out[(size_t)(row0 + 8) * DD + col] = make_float2(f[2], f[3]);
            }
    }
}

// ---------------- zero accumulators (vsum + rowsum) ----------------
__global__ void vsum_zero_kernel() {
    int i = blockIdx.x * 256 + threadIdx.x;
    g_vsum[i] = 0.f;
    if (i < NBH * UMAX) g_rowsum[i] = 0.f;
}

__global__ void vsum_kernel() {
    int b = blockIdx.z;
    int d = blockIdx.x * 256 + threadIdx.x;
    int l0 = blockIdx.y * 256;
    const float* p = g_V + ((size_t)b * LL + l0) * DD + d;
    float s = 0.f;
#pragma unroll 8
    for (int l = 0; l < 256; l++) s += p[(size_t)l * DD];
    atomicAdd(&g_vsum[b * DD + d], s);
}

// ---------------- M stage (round-9 batched-butterfly version) ----------------
__global__ void __launch_bounds__(256)
mstage_kernel(const int* __restrict__ sidx, int SK)
{
    int w = blockIdx.x * 8 + (threadIdx.x >> 5);
    int lane = threadIdx.x & 31;
    int b = w >> 12;
    int q = w & (LL - 1);

    const float4* qrow = (const float4*)(g_Q + (size_t)(b * LL + q) * DD);
    float4 qv[4];
#pragma unroll
    for (int c = 0; c < 4; c++) qv[c] = qrow[c * 32 + lane];

    float mxL[4], smL[4];
#pragma unroll
    for (int c = 0; c < 4; c++) { mxL[c] = -3.4e38f; smL[c] = 0.f; }

    const int* sp = sidx + (size_t)q * SK;
    int idxA = (lane < SK) ? __ldg(sp + lane) : 0;
    int idxB = (32 + lane < SK) ? __ldg(sp + 32 + lane) : 0;
    const float* kbase_p = g_K + (size_t)b * LL * DD;

    const int mysamp_off = (lane >> 2) & 3;
    const bool amLeader = ((lane & 3) == 0);

    for (int base = 0; base < SK; base += 4) {
        float d[4][4];
#pragma unroll
        for (int c = 0; c < 4; c++)
#pragma unroll
            for (int j = 0; j < 4; j++) d[c][j] = 0.f;
        int nb = SK - base; if (nb > 4) nb = 4;
        for (int s = 0; s < nb; s++) {
            int src = base + s;
            int idx = __shfl_sync(0xffffffffu, (src < 32) ? idxA : idxB, src & 31);
            const float4* kr = (const float4*)(kbase_p + (size_t)idx * DD);
#pragma unroll
            for (int c = 0; c < 4; c++) {
                float4 kv = kr[c * 32 + lane];
                d[c][s] = qv[c].x * kv.x + qv[c].y * kv.y + qv[c].z * kv.z + qv[c].w * kv.w;
            }
        }
#pragma unroll
        for (int c = 0; c < 4; c++) {
            float s0 = (lane & 8) ? d[c][0] : d[c][2];
            float s1 = (lane & 8) ? d[c][1] : d[c][3];
            float r0 = __shfl_xor_sync(0xffffffffu, s0, 8);
            float r1 = __shfl_xor_sync(0xffffffffu, s1, 8);
            float e0 = ((lane & 8) ? d[c][2] : d[c][0]) + r0;
            float e1 = ((lane & 8) ? d[c][3] : d[c][1]) + r1;
            float t0 = (lane & 4) ? e0 : e1;
            float g = ((lane & 4) ? e1 : e0) + __shfl_xor_sync(0xffffffffu, t0, 4);
            g += __shfl_xor_sync(0xffffffffu, g, 2);
            g += __shfl_xor_sync(0xffffffffu, g, 1);
            int samp = base + mysamp_off;
            if (amLeader && samp < SK) {
                mxL[c] = fmaxf(mxL[c], g);
                smL[c] += g;
            }
        }
    }

#pragma unroll
    for (int c = 0; c < 4; c++) {
        mxL[c] = fmaxf(mxL[c], __shfl_xor_sync(0xffffffffu, mxL[c], 4));
        smL[c] += __shfl_xor_sync(0xffffffffu, smL[c], 4);
        mxL[c] = fmaxf(mxL[c], __shfl_xor_sync(0xffffffffu, mxL[c], 8));
        smL[c] += __shfl_xor_sync(0xffffffffu, smL[c], 8);
    }
    if ((lane & 15) == 0) {
        int half = lane >> 4;
        float invSK = 1.f / (float)SK;
#pragma unroll
        for (int c = 0; c < 4; c++) {
            int h = c * 2 + half;
            g_M[((size_t)(b * HH + h)) * LL + q] = mxL[c] - smL[c] * invSK;
        }
    }
}

// ---------------- top-u selection: per-warp extraction + 32-way merge ----------------
__global__ void __launch_bounds__(1024)
topk_kernel(int u)
{
    __shared__ unsigned long long cand[32 * UMAX];
    int bh = blockIdx.x;
    int tid = threadIdx.x;
    int w = tid >> 5, lane = tid & 31;

    unsigned long long key[4];
#pragma unroll
    for (int r = 0; r < 4; r++) {
        int i = w * 128 + r * 32 + lane;
        unsigned int s = __float_as_uint(g_M[(size_t)bh * LL + i]);
        s = (s & 0x80000000u) ? ~s : (s | 0x80000000u);
        key[r] = ((unsigned long long)s << 32) | (unsigned int)(~i);
    }
    for (int r = 0; r < u; r++) {
        unsigned long long m0 = key[0] > key[1] ? key[0] : key[1];
        unsigned long long m1 = key[2] > key[3] ? key[2] : key[3];
        unsigned long long m = m0 > m1 ? m0 : m1;
#pragma unroll
        for (int s = 16; s > 0; s >>= 1) {
            unsigned long long o = __shfl_xor_sync(0xffffffffu, m, s);
            if (o > m) m = o;
        }
#pragma unroll
        for (int j = 0; j < 4; j++) if (key[j] == m) key[j] = 0ull;
        if (lane == 0) cand[w * UMAX + r] = m;
    }
    __syncthreads();
    if (w == 0) {
        int pos = 0;
        unsigned long long head = cand[lane * UMAX];
        for (int r = 0; r < u; r++) {
            unsigned long long m = head;
#pragma unroll
            for (int s = 16; s > 0; s >>= 1) {
                unsigned long long o = __shfl_xor_sync(0xffffffffu, m, s);
                if (o > m) m = o;
            }
            if (head == m) {
                g_top[bh * UMAX + r] = (int)(~(unsigned int)m);
                pos++;
                head = (pos < u) ? cand[lane * UMAX + pos] : 0ull;
            }
        }
    }
}

// ---------------- scores + fused exp + row-sum accumulation ----------------
// Writes P = exp(score) (unnormalized; softmax max-shift dropped — scores are
// provably tiny: sigma~0.2, so exp never overflows) and accumulates row sums
// into g_rowsum. The separate softmax kernel is deleted; normalization happens
// in corr_kernel. This removes a full 48MB read+write of g_S.
__global__ void __launch_bounds__(256)
scores_kernel(int u)
{
    int bh = blockIdx.y;
    int b = bh >> 3, h = bh & 7;
    int kbase = blockIdx.x * 128;
    __shared__ float Qs[UMAX][64];
    __shared__ float Ks[64][130];
    int tid = threadIdx.x;

    for (int idx = tid; idx < UMAX * 64; idx += 256) {
        int q = idx >> 6, e = idx & 63;
        float v = 0.f;
        if (q < u) {
            int row = g_top[bh * UMAX + q];
            v = g_Q[(size_t)(b * LL + row) * DD + h * EE + e];
        }
        Qs[q][e] = v;
    }
    for (int idx = tid; idx < 128 * 64; idx += 256) {
        int k = idx >> 6, e = idx & 63;
        Ks[e][k] = g_K[(size_t)(b * LL + kbase + k) * DD + h * EE + e];
    }
    __syncthreads();

    int tx = tid & 31, ty = tid >> 5;
    float acc[6][4];
#pragma unroll
    for (int j = 0; j < 6; j++)
#pragma unroll
        for (int i = 0; i < 4; i++) acc[j][i] = 0.f;

#pragma unroll 8
    for (int e = 0; e < 64; e++) {
        float2 ka = *(const float2*)&Ks[e][tx * 4];
        float2 kb = *(const float2*)&Ks[e][tx * 4 + 2];
#pragma unroll
        for (int j = 0; j < 6; j++) {
            float qv = Qs[ty + 8 * j][e];
            acc[j][0] = fmaf(qv, ka.x, acc[j][0]);
            acc[j][1] = fmaf(qv, ka.y, acc[j][1]);
            acc[j][2] = fmaf(qv, kb.x, acc[j][2]);
            acc[j][3] = fmaf(qv, kb.y, acc[j][3]);
        }
    }
    const float scale = 0.125f;
#pragma unroll
    for (int j = 0; j < 6; j++) {
        int q = ty + 8 * j;              // uniform across the warp (ty = warp id)
        if (q < u) {
            float p0 = fexp(acc[j][0] * scale);
            float p1 = fexp(acc[j][1] * scale);
            float p2 = fexp(acc[j][2] * scale);
            float p3 = fexp(acc[j][3] * scale);
            *(float4*)&g_S[((size_t)bh * UMAX + q) * LL + kbase + tx * 4] =
                make_float4(p0, p1, p2, p3);
            float rs = (p0 + p1) + (p2 + p3);
            rs += __shfl_xor_sync(0xffffffffu, rs, 16);
            rs += __shfl_xor_sync(0xffffffffu, rs, 8);
            rs += __shfl_xor_sync(0xffffffffu, rs, 4);
            rs += __shfl_xor_sync(0xffffffffu, rs, 2);
            rs += __shfl_xor_sync(0xffffffffu, rs, 1);
            if (tx == 0) atomicAdd(&g_rowsum[bh * UMAX + q], rs);
        }
    }
}

// ---------------- ctx partials (consumes unnormalized P) ----------------
__global__ void __launch_bounds__(256)
ctx_kernel(int u)
{
    int split = blockIdx.x;
    int bh = blockIdx.y;
    int b = bh >> 3, h = bh & 7;
    __shared__ float Vt[64][64];
    __shared__ float St[UMAX][64];
    int tid = threadIdx.x;
    int e = tid & 63, qs = tid >> 6;

    float acc[11];
#pragma unroll
    for (int j = 0; j < 11; j++) acc[j] = 0.f;

    int k0 = split * (LL / NSPLIT);
    for (int t = 0; t < (LL / NSPLIT) / 64; t++) {
        int kb = k0 + t * 64;
        for (int idx = tid; idx < 64 * 64; idx += 256) {
            int kk = idx >> 6, ee = idx & 63;
            Vt[kk][ee] = g_V[(size_t)(b * LL + kb + kk) * DD + h * EE + ee];
        }
        for (int idx = tid; idx < UMAX * 64; idx += 256) {
            int q = idx >> 6, kk = idx & 63;
            St[q][kk] = (q < u) ? g_S[((size_t)bh * UMAX + q) * LL + kb + kk] : 0.f;
        }
        __syncthreads();
#pragma unroll 4
        for (int kk = 0; kk < 64; kk++) {
            float v = Vt[kk][e];
#pragma unroll
            for (int j = 0; j < 11; j++)
                acc[j] = fmaf(St[qs + 4 * j][kk], v, acc[j]);
        }
        __syncthreads();
    }
#pragma unroll
    for (int j = 0; j < 11; j++) {
        int q = qs + 4 * j;
        if (q < u)
            g_ctxP[(((size_t)split * NBH + bh) * UMAX + q) * EE + e] = acc[j];
    }
}

// ---------------- base row per batch ----------------
__global__ void __launch_bounds__(512)
base_kernel(const float* __restrict__ Wout, const float* __restrict__ bout)
{
    int b = blockIdx.x;
    int o = threadIdx.x;
    __shared__ float vm[DD];
    vm[o] = g_vsum[b * DD + o] * (1.f / (float)LL);
    __syncthreads();
    float acc = bout[o];
#pragma unroll 8
    for (int d = 0; d < DD; d++) acc = fmaf(vm[d], Wout[(size_t)d * DD + o], acc);
    g_base[b * DD + o] = acc;
}

// ---------------- broadcast base row ----------------
__global__ void fill_kernel(float* __restrict__ out)
{
    size_t idx = (size_t)blockIdx.x * 256 + threadIdx.x;
    int c = (int)(idx & 127);
    int r = (int)(idx >> 7);
    int b = r >> 12;
    ((float4*)out)[idx] = ((const float4*)(g_base + b * DD))[c];
}

// ---------------- rank-64 corrections (normalizes by rowsum) ----------------
__global__ void __launch_bounds__(128)
corr_kernel(float* __restrict__ out, const float* __restrict__ Wout)
{
    int qs = blockIdx.x;
    int bh = blockIdx.y;
    int b = bh >> 3, h = bh & 7;
    __shared__ float delta[EE];
    __shared__ int qidx_s;
    int tid = threadIdx.x;
    if (tid < EE) {
        float s = 0.f;
#pragma unroll
        for (int sp = 0; sp < NSPLIT; sp++)
            s += g_ctxP[(((size_t)sp * NBH + bh) * UMAX + qs) * EE + tid];
        float rinv = 1.f / g_rowsum[bh * UMAX + qs];
        delta[tid] = s * rinv - g_vsum[b * DD + h * EE + tid] * (1.f / (float)LL);
    }
    if (tid == 0) qidx_s = g_top[bh * UMAX + qs];
    __syncthreads();
    float* orow = out + (size_t)(b * LL + qidx_s) * DD;
    for (int o = tid; o < DD; o += 128) {
        float acc = 0.f;
#pragma unroll 8
        for (int e = 0; e < EE; e++)
            acc = fmaf(delta[e], Wout[(size_t)(h * EE + e) * DD + o], acc);
        atomicAdd(&orow[o], acc);
    }
}

// ---------------- launch ----------------
extern "C" void kernel_launch(void* const* d_in, const int* in_sizes, int n_in,
                              void* d_out, int out_size)
{
    const float* query  = (const float*)d_in[0];
    const float* key_in = (const float*)d_in[1];
    const float* value  = (const float*)d_in[2];
    const float* W_Q    = (const float*)d_in[3];
    const float* W_K    = (const float*)d_in[4];
    const float* W_V    = (const float*)d_in[5];
    const float* W_out  = (const float*)d_in[6];
    const float* b_out  = (const float*)d_in[7];
    const int*   sidx   = (const int*)d_in[8];
    float* out = (float*)d_out;

    int SK = in_sizes[8] / LL;
    int u = (int)(5.0 * log((double)LL + 1.0));
    if (u < 1) u = 1;
    if (u > UMAX) u = UMAX;

    float *pQ, *pK, *pV;
    cudaGetSymbolAddress((void**)&pQ, g_Q);
    cudaGetSymbolAddress((void**)&pK, g_K);
    cudaGetSymbolAddress((void**)&pV, g_V);

    cudaFuncSetAttribute(hmma_gemm_kernel, cudaFuncAttributeMaxDynamicSharedMemorySize, GEMM_SMEM);

    // mstage stays in the profiled slot (control measurement).
    splitA_kernel<<<dim3(16384, 3), 256>>>(query, key_in, value);      // 0
    splitW_kernel<<<dim3(16, 16, 3), dim3(32, 32)>>>(W_Q, W_K, W_V);   // 1
    hmma_gemm_kernel<<<dim3(4, 256, 3), 256, GEMM_SMEM>>>(pQ, pK, pV); // 2
    mstage_kernel<<<NROWS / 8, 256>>>(sidx, SK);                       // 3  <- profiled slot
    vsum_zero_kernel<<<BB * DD / 256, 256>>>();                        // 4
    vsum_kernel<<<dim3(2, 16, BB), 256>>>();                           // 5

    topk_kernel<<<NBH, 1024>>>(u);

    scores_kernel<<<dim3(LL / 128, NBH), 256>>>(u);   // exp + rowsum fused; softmax deleted
    ctx_kernel<<<dim3(NSPLIT, NBH), 256>>>(u);

    base_kernel<<<BB, 512>>>(W_out, b_out);
    fill_kernel<<<(size_t)BB * LL * DD / 4 / 256, 256>>>(out);
    corr_kernel<<<dim3(u, NBH), 128>>>(out, W_out);
}

// round 15
// speedup vs baseline: 1.4626x; 1.4626x over previous
#include <cuda_runtime.h>
#include <cuda_bf16.h>
#include <math.h>
#include <stdint.h>

// Problem constants (fixed shapes for this problem)
#define BB   8
#define LL   4096
#define DD   512
#define HH   8
#define EE   64
#define UMAX 48
#define NROWS (BB*LL)          // 32768
#define NBH   (BB*HH)          // 64
#define NSPLIT 8               // K-splits for ctx GEMM

// ---------------- scratch (static device allocations, allowed) ----------------
__device__ float g_Q[(size_t)NROWS*DD];                  // 64 MB, natural (b,l,d)
__device__ float g_K[(size_t)NROWS*DD];                  // 64 MB
__device__ float g_V[(size_t)NROWS*DD];                  // 64 MB
__device__ float g_M[(size_t)NBH*LL];                    // 1 MB
__device__ int   g_top[NBH*UMAX];                        // top-u indices per (b,h)
__device__ float g_S[(size_t)NBH*UMAX*LL];               // 48 MB: exp(scores), unnormalized
__device__ float g_rowsum[NBH*UMAX];                     // per-(bh,q) sum of exp
__device__ float g_ctxP[(size_t)NSPLIT*NBH*UMAX*EE];     // 6 MB partial ctx
__device__ float g_vsum[BB*DD];                          // V column sums per batch
__device__ float g_base[BB*DD];                          // base output row per batch

// bf16 split operands for tensor-core projections
__device__ __nv_bfloat16 g_Ah[(size_t)3*NROWS*DD];       // 96 MB
__device__ __nv_bfloat16 g_Al[(size_t)3*NROWS*DD];       // 96 MB
__device__ __nv_bfloat16 g_Wth[(size_t)3*DD*DD];         // W^T hi  [n][k]
__device__ __nv_bfloat16 g_Wtl[(size_t)3*DD*DD];         // W^T lo  [n][k]

// ================= helpers =================
__device__ __forceinline__ uint32_t smem_u32(const void* p) {
    uint32_t a;
    asm("{ .reg .u64 t; cvta.to.shared.u64 t, %1; cvt.u32.u64 %0, t; }" : "=r"(a) : "l"(p));
    return a;
}

// FMA-pipe exp (no MUFU): x*log2e, magic-number round, degree-6 2^f Taylor,
// exponent splice by integer add. ~1e-7 rel err. Clamped to [-87, 80].
__device__ __forceinline__ float fexp(float x) {
    x = fmaxf(fminf(x, 80.0f), -87.0f);
    float t = x * 1.4426950408889634f;
    float r = t + 12582912.0f;                   // 1.5 * 2^23 magic RN
    int   k = __float_as_int(r) - 0x4B400000;    // round(t) as integer
    float f = t - (r - 12582912.0f);             // t - round(t), in [-0.5, 0.5]
    float p = 1.5402387e-4f;
    p = fmaf(p, f, 1.3333558e-3f);
    p = fmaf(p, f, 9.6181291e-3f);
    p = fmaf(p, f, 5.5504109e-2f);
    p = fmaf(p, f, 2.4022651e-1f);
    p = fmaf(p, f, 6.9314718e-1f);
    p = fmaf(p, f, 1.0f);
    return __int_as_float(__float_as_int(p) + (k << 23));
}

#define CP_ASYNC16(dst, src) \
    asm volatile("cp.async.ca.shared.global [%0], [%1], 16;" :: "r"(dst), "l"(src) : "memory")
#define CP_COMMIT() asm volatile("cp.async.commit_group;" ::: "memory")
#define CP_WAIT2()  asm volatile("cp.async.wait_group 2;" ::: "memory")

#define LDM4(r, addr) \
    asm volatile("ldmatrix.sync.aligned.m8n8.x4.shared.b16 {%0,%1,%2,%3}, [%4];" \
        : "=r"((r)[0]), "=r"((r)[1]), "=r"((r)[2]), "=r"((r)[3]) : "r"(addr))

#define MMA16816(d, a, b0, b1) \
    asm volatile("mma.sync.aligned.m16n8k16.row.col.f32.bf16.bf16.f32 " \
        "{%0,%1,%2,%3}, {%4,%5,%6,%7}, {%8,%9}, {%0,%1,%2,%3};" \
        : "+f"((d)[0]), "+f"((d)[1]), "+f"((d)[2]), "+f"((d)[3]) \
        : "r"((a)[0]), "r"((a)[1]), "r"((a)[2]), "r"((a)[3]), "r"(b0), "r"(b1))

// ---------------- split kernels ----------------
__global__ void __launch_bounds__(256)
splitA_kernel(const float* __restrict__ q, const float* __restrict__ k, const float* __restrict__ v)
{
    int z = blockIdx.y;
    const float* src = (z == 0) ? q : ((z == 1) ? k : v);
    size_t i4 = (size_t)blockIdx.x * 256 + threadIdx.x;
    float4 a = ((const float4*)src)[i4];
    __nv_bfloat16 hx = __float2bfloat16_rn(a.x);
    __nv_bfloat16 hy = __float2bfloat16_rn(a.y);
    __nv_bfloat16 hz = __float2bfloat16_rn(a.z);
    __nv_bfloat16 hw = __float2bfloat16_rn(a.w);
    __nv_bfloat16 lx = __float2bfloat16_rn(a.x - __bfloat162float(hx));
    __nv_bfloat16 ly = __float2bfloat16_rn(a.y - __bfloat162float(hy));
    __nv_bfloat16 lz = __float2bfloat16_rn(a.z - __bfloat162float(hz));
    __nv_bfloat16 lw = __float2bfloat16_rn(a.w - __bfloat162float(hw));
    __nv_bfloat162* dh = (__nv_bfloat162*)(g_Ah + (size_t)z * NROWS * DD);
    __nv_bfloat162* dl = (__nv_bfloat162*)(g_Al + (size_t)z * NROWS * DD);
    dh[i4 * 2]     = __halves2bfloat162(hx, hy);
    dh[i4 * 2 + 1] = __halves2bfloat162(hz, hw);
    dl[i4 * 2]     = __halves2bfloat162(lx, ly);
    dl[i4 * 2 + 1] = __halves2bfloat162(lz, lw);
}

__global__ void splitW_kernel(const float* __restrict__ WQ, const float* __restrict__ WK,
                              const float* __restrict__ WV)
{
    __shared__ float t[32][33];
    int z = blockIdx.z;
    const float* W = (z == 0) ? WQ : ((z == 1) ? WK : WV);
    int k = blockIdx.y * 32 + threadIdx.y;
    int n = blockIdx.x * 32 + threadIdx.x;
    t[threadIdx.y][threadIdx.x] = W[(size_t)k * DD + n];
    __syncthreads();
    int n2 = blockIdx.x * 32 + threadIdx.y;
    int k2 = blockIdx.y * 32 + threadIdx.x;
    float v = t[threadIdx.x][threadIdx.y];
    __nv_bfloat16 h = __float2bfloat16_rn(v);
    __nv_bfloat16 l = __float2bfloat16_rn(v - __bfloat162float(h));
    g_Wth[(size_t)z * DD * DD + (size_t)n2 * DD + k2] = h;
    g_Wtl[(size_t)z * DD * DD + (size_t)n2 * DD + k2] = l;
}

// ---------------- HMMA projection GEMM (round-6 best config) ----------------
#define NSTAGE  4
#define STAGE_B 16384        // A: 128*64B = 8192 ; W: 128*64B = 8192
#define GEMM_SMEM (NSTAGE*STAGE_B)   // 65536
#define KITER 48             // 1536 / 32

__global__ void __launch_bounds__(256, 2)
hmma_gemm_kernel(float* __restrict__ outQ, float* __restrict__ outK, float* __restrict__ outV)
{
    extern __shared__ char smem[];
    const uint32_t sb = smem_u32(smem);
    const int tid = threadIdx.x;
    const int z = blockIdx.z;
    const int mBase = blockIdx.y * 128;
    const int nBase = blockIdx.x * 128;

    const __nv_bfloat16* __restrict__ Ah = g_Ah + (size_t)z * NROWS * DD;
    const __nv_bfloat16* __restrict__ Al = g_Al + (size_t)z * NROWS * DD;
    const __nv_bfloat16* __restrict__ Wh = g_Wth + (size_t)z * DD * DD;
    const __nv_bfloat16* __restrict__ Wl = g_Wtl + (size_t)z * DD * DD;
    float* __restrict__ out = (z == 0) ? outQ : ((z == 1) ? outK : outV);

    const int r0 = tid >> 2, c0 = tid & 3;
    const int r1 = (tid + 256) >> 2, c1 = tid & 3;
    const uint32_t aDst0 = sb + r0 * 64 + ((c0 ^ ((r0 >> 1) & 3)) * 16);
    const uint32_t aDst1 = sb + r1 * 64 + ((c1 ^ ((r1 >> 1) & 3)) * 16);
    const uint32_t wDst0 = aDst0 + 8192;
    const uint32_t wDst1 = aDst1 + 8192;
    const size_t aSrc0 = (size_t)(mBase + r0) * DD + c0 * 8;
    const size_t aSrc1 = (size_t)(mBase + r1) * DD + c1 * 8;
    const size_t wSrc0 = (size_t)(nBase + r0) * DD + c0 * 8;
    const size_t wSrc1 = (size_t)(nBase + r1) * DD + c1 * 8;

    const int wid = tid >> 5, lane = tid & 31;
    const int warp_m = (wid >> 1) * 32;
    const int warp_n = (wid & 1) * 64;
    const int lrow = lane & 15;
    const int lkc = lane >> 4;
    const int xr = (lrow >> 1) & 3;
    uint32_t aAddr[2], wAddr[4];
#pragma unroll
    for (int mf = 0; mf < 2; mf++) aAddr[mf] = sb + (warp_m + mf * 16 + lrow) * 64;
#pragma unroll
    for (int nf = 0; nf < 4; nf++) wAddr[nf] = sb + 8192 + (warp_n + nf * 16 + lrow) * 64;

    float acc[2][8][4];
#pragma unroll
    for (int mf = 0; mf < 2; mf++)
#pragma unroll
        for (int ns = 0; ns < 8; ns++)
#pragma unroll
            for (int e = 0; e < 4; e++) acc[mf][ns][e] = 0.f;

#pragma unroll
    for (int s = 0; s < NSTAGE - 1; s++) {
        int kt = s * 32;
        int r = kt >> 9, kk = kt & 511;
        const __nv_bfloat16* As_ = (r == 1) ? Al : Ah;
        const __nv_bfloat16* Ws_ = (r == 2) ? Wl : Wh;
        uint32_t so = (uint32_t)s * STAGE_B;
        CP_ASYNC16(aDst0 + so, As_ + aSrc0 + kk);
        CP_ASYNC16(aDst1 + so, As_ + aSrc1 + kk);
        CP_ASYNC16(wDst0 + so, Ws_ + wSrc0 + kk);
        CP_ASYNC16(wDst1 + so, Ws_ + wSrc1 + kk);
        CP_COMMIT();
    }

    for (int it = 0; it < KITER; it++) {
        CP_WAIT2();
        __syncthreads();
        int nit = it + NSTAGE - 1;
        if (nit < KITER) {
            int kt = nit * 32;
            int r = kt >> 9, kk = kt & 511;
            const __nv_bfloat16* As_ = (r == 1) ? Al : Ah;
            const __nv_bfloat16* Ws_ = (r == 2) ? Wl : Wh;
            uint32_t so2 = (uint32_t)(nit & 3) * STAGE_B;
            CP_ASYNC16(aDst0 + so2, As_ + aSrc0 + kk);
            CP_ASYNC16(aDst1 + so2, As_ + aSrc1 + kk);
            CP_ASYNC16(wDst0 + so2, Ws_ + wSrc0 + kk);
            CP_ASYNC16(wDst1 + so2, Ws_ + wSrc1 + kk);
        }
        CP_COMMIT();

        uint32_t so = (uint32_t)(it & 3) * STAGE_B;
#pragma unroll
        for (int ks = 0; ks < 2; ks++) {
            uint32_t csOff = (uint32_t)((((ks << 1) | lkc) ^ xr) * 16) + so;
            uint32_t a[2][4], b[4][4];
#pragma unroll
            for (int mf = 0; mf < 2; mf++) LDM4(a[mf], aAddr[mf] + csOff);
#pragma unroll
            for (int nf = 0; nf < 4; nf++) LDM4(b[nf], wAddr[nf] + csOff);
#pragma unroll
            for (int mf = 0; mf < 2; mf++)
#pragma unroll
                for (int nf = 0; nf < 4; nf++) {
                    MMA16816(acc[mf][nf * 2],     a[mf], b[nf][0], b[nf][2]);
                    MMA16816(acc[mf][nf * 2 + 1], a[mf], b[nf][1], b[nf][3]);
                }
        }
    }

    const int tg = lane >> 2;
    const int tc = (lane & 3) * 2;
#pragma unroll
    for (int mf = 0; mf < 2; mf++) {
        int row0 = mBase + warp_m + mf * 16 + tg;
#pragma unroll
        for (int nf = 0; nf < 4; nf++)
#pragma unroll
            for (int sub = 0; sub < 2; sub++) {
                float* f = acc[mf][nf * 2 + sub];
                int col = nBase + warp_n + nf * 16 + sub * 8 + tc;
                *(float2*)&out[(size_t)row0 * DD + col]       = make_float2(f[0], f[1]);
                *(float2*)&out[(size_t)(row0 + 8) * DD + col] = make_float2(f[2], f[3]);
            }
    }
}

// ---------------- zero accumulators (vsum + rowsum) ----------------
__global__ void vsum_zero_kernel() {
    int i = blockIdx.x * 256 + threadIdx.x;
    g_vsum[i] = 0.f;
    if (i < NBH * UMAX) g_rowsum[i] = 0.f;
}

__global__ void vsum_kernel() {
    int b = blockIdx.z;
    int d = blockIdx.x * 256 + threadIdx.x;
    int l0 = blockIdx.y * 256;
    const float* p = g_V + ((size_t)b * LL + l0) * DD + d;
    float s = 0.f;
#pragma unroll 8
    for (int l = 0; l < 256; l++) s += p[(size_t)l * DD];
    atomicAdd(&g_vsum[b * DD + d], s);
}

// ---------------- M stage (round-9 batched-butterfly version) ----------------
__global__ void __launch_bounds__(256)
mstage_kernel(const int* __restrict__ sidx, int SK)
{
    int w = blockIdx.x * 8 + (threadIdx.x >> 5);
    int lane = threadIdx.x & 31;
    int b = w >> 12;
    int q = w & (LL - 1);

    const float4* qrow = (const float4*)(g_Q + (size_t)(b * LL + q) * DD);
    float4 qv[4];
#pragma unroll
    for (int c = 0; c < 4; c++) qv[c] = qrow[c * 32 + lane];

    float mxL[4], smL[4];
#pragma unroll
    for (int c = 0; c < 4; c++) { mxL[c] = -3.4e38f; smL[c] = 0.f; }

    const int* sp = sidx + (size_t)q * SK;
    int idxA = (lane < SK) ? __ldg(sp + lane) : 0;
    int idxB = (32 + lane < SK) ? __ldg(sp + 32 + lane) : 0;
    const float* kbase_p = g_K + (size_t)b * LL * DD;

    const int mysamp_off = (lane >> 2) & 3;
    const bool amLeader = ((lane & 3) == 0);

    for (int base = 0; base < SK; base += 4) {
        float d[4][4];
#pragma unroll
        for (int c = 0; c < 4; c++)
#pragma unroll
            for (int j = 0; j < 4; j++) d[c][j] = 0.f;
        int nb = SK - base; if (nb > 4) nb = 4;
        for (int s = 0; s < nb; s++) {
            int src = base + s;
            int idx = __shfl_sync(0xffffffffu, (src < 32) ? idxA : idxB, src & 31);
            const float4* kr = (const float4*)(kbase_p + (size_t)idx * DD);
#pragma unroll
            for (int c = 0; c < 4; c++) {
                float4 kv = kr[c * 32 + lane];
                d[c][s] = qv[c].x * kv.x + qv[c].y * kv.y + qv[c].z * kv.z + qv[c].w * kv.w;
            }
        }
#pragma unroll
        for (int c = 0; c < 4; c++) {
            float s0 = (lane & 8) ? d[c][0] : d[c][2];
            float s1 = (lane & 8) ? d[c][1] : d[c][3];
            float r0 = __shfl_xor_sync(0xffffffffu, s0, 8);
            float r1 = __shfl_xor_sync(0xffffffffu, s1, 8);
            float e0 = ((lane & 8) ? d[c][2] : d[c][0]) + r0;
            float e1 = ((lane & 8) ? d[c][3] : d[c][1]) + r1;
            float t0 = (lane & 4) ? e0 : e1;
            float g = ((lane & 4) ? e1 : e0) + __shfl_xor_sync(0xffffffffu, t0, 4);
            g += __shfl_xor_sync(0xffffffffu, g, 2);
            g += __shfl_xor_sync(0xffffffffu, g, 1);
            int samp = base + mysamp_off;
            if (amLeader && samp < SK) {
                mxL[c] = fmaxf(mxL[c], g);
                smL[c] += g;
            }
        }
    }

#pragma unroll
    for (int c = 0; c < 4; c++) {
        mxL[c] = fmaxf(mxL[c], __shfl_xor_sync(0xffffffffu, mxL[c], 4));
        smL[c] += __shfl_xor_sync(0xffffffffu, smL[c], 4);
        mxL[c] = fmaxf(mxL[c], __shfl_xor_sync(0xffffffffu, mxL[c], 8));
        smL[c] += __shfl_xor_sync(0xffffffffu, smL[c], 8);
    }
    if ((lane & 15) == 0) {
        int half = lane >> 4;
        float invSK = 1.f / (float)SK;
#pragma unroll
        for (int c = 0; c < 4; c++) {
            int h = c * 2 + half;
            g_M[((size_t)(b * HH + h)) * LL + q] = mxL[c] - smL[c] * invSK;
        }
    }
}

// ---------------- top-u selection: per-warp extraction + 32-way merge ----------------
__global__ void __launch_bounds__(1024)
topk_kernel(int u)
{
    __shared__ unsigned long long cand[32 * UMAX];
    int bh = blockIdx.x;
    int tid = threadIdx.x;
    int w = tid >> 5, lane = tid & 31;

    unsigned long long key[4];
#pragma unroll
    for (int r = 0; r < 4; r++) {
        int i = w * 128 + r * 32 + lane;
        unsigned int s = __float_as_uint(g_M[(size_t)bh * LL + i]);
        s = (s & 0x80000000u) ? ~s : (s | 0x80000000u);
        key[r] = ((unsigned long long)s << 32) | (unsigned int)(~i);
    }
    for (int r = 0; r < u; r++) {
        unsigned long long m0 = key[0] > key[1] ? key[0] : key[1];
        unsigned long long m1 = key[2] > key[3] ? key[2] : key[3];
        unsigned long long m = m0 > m1 ? m0 : m1;
#pragma unroll
        for (int s = 16; s > 0; s >>= 1) {
            unsigned long long o = __shfl_xor_sync(0xffffffffu, m, s);
            if (o > m) m = o;
        }
#pragma unroll
        for (int j = 0; j < 4; j++) if (key[j] == m) key[j] = 0ull;
        if (lane == 0) cand[w * UMAX + r] = m;
    }
    __syncthreads();
    if (w == 0) {
        int pos = 0;
        unsigned long long head = cand[lane * UMAX];
        for (int r = 0; r < u; r++) {
            unsigned long long m = head;
#pragma unroll
            for (int s = 16; s > 0; s >>= 1) {
                unsigned long long o = __shfl_xor_sync(0xffffffffu, m, s);
                if (o > m) m = o;
            }
            if (head == m) {
                g_top[bh * UMAX + r] = (int)(~(unsigned int)m);
                pos++;
                head = (pos < u) ? cand[lane * UMAX + pos] : 0ull;
            }
        }
    }
}

// ---------------- scores + fused exp + row-sum accumulation ----------------
__global__ void __launch_bounds__(256)
scores_kernel(int u)
{
    int bh = blockIdx.y;
    int b = bh >> 3, h = bh & 7;
    int kbase = blockIdx.x * 128;
    __shared__ float Qs[UMAX][64];
    __shared__ float Ks[64][130];
    int tid = threadIdx.x;

    for (int idx = tid; idx < UMAX * 64; idx += 256) {
        int q = idx >> 6, e = idx & 63;
        float v = 0.f;
        if (q < u) {
            int row = g_top[bh * UMAX + q];
            v = g_Q[(size_t)(b * LL + row) * DD + h * EE + e];
        }
        Qs[q][e] = v;
    }
    for (int idx = tid; idx < 128 * 64; idx += 256) {
        int k = idx >> 6, e = idx & 63;
        Ks[e][k] = g_K[(size_t)(b * LL + kbase + k) * DD + h * EE + e];
    }
    __syncthreads();

    int tx = tid & 31, ty = tid >> 5;
    float acc[6][4];
#pragma unroll
    for (int j = 0; j < 6; j++)
#pragma unroll
        for (int i = 0; i < 4; i++) acc[j][i] = 0.f;

#pragma unroll 8
    for (int e = 0; e < 64; e++) {
        float2 ka = *(const float2*)&Ks[e][tx * 4];
        float2 kb = *(const float2*)&Ks[e][tx * 4 + 2];
#pragma unroll
        for (int j = 0; j < 6; j++) {
            float qv = Qs[ty + 8 * j][e];
            acc[j][0] = fmaf(qv, ka.x, acc[j][0]);
            acc[j][1] = fmaf(qv, ka.y, acc[j][1]);
            acc[j][2] = fmaf(qv, kb.x, acc[j][2]);
            acc[j][3] = fmaf(qv, kb.y, acc[j][3]);
        }
    }
    const float scale = 0.125f;
#pragma unroll
    for (int j = 0; j < 6; j++) {
        int q = ty + 8 * j;              // uniform across the warp (ty = warp id)
        if (q < u) {
            float p0 = fexp(acc[j][0] * scale);
            float p1 = fexp(acc[j][1] * scale);
            float p2 = fexp(acc[j][2] * scale);
            float p3 = fexp(acc[j][3] * scale);
            *(float4*)&g_S[((size_t)bh * UMAX + q) * LL + kbase + tx * 4] =
                make_float4(p0, p1, p2, p3);
            float rs = (p0 + p1) + (p2 + p3);
            rs += __shfl_xor_sync(0xffffffffu, rs, 16);
            rs += __shfl_xor_sync(0xffffffffu, rs, 8);
            rs += __shfl_xor_sync(0xffffffffu, rs, 4);
            rs += __shfl_xor_sync(0xffffffffu, rs, 2);
            rs += __shfl_xor_sync(0xffffffffu, rs, 1);
            if (tx == 0) atomicAdd(&g_rowsum[bh * UMAX + q], rs);
        }
    }
}

// ---------------- ctx partials (consumes unnormalized P) ----------------
__global__ void __launch_bounds__(256)
ctx_kernel(int u)
{
    int split = blockIdx.x;
    int bh = blockIdx.y;
    int b = bh >> 3, h = bh & 7;
    __shared__ float Vt[64][64];
    __shared__ float St[UMAX][64];
    int tid = threadIdx.x;
    int e = tid & 63, qs = tid >> 6;

    float acc[11];
#pragma unroll
    for (int j = 0; j < 11; j++) acc[j] = 0.f;

    int k0 = split * (LL / NSPLIT);
    for (int t = 0; t < (LL / NSPLIT) / 64; t++) {
        int kb = k0 + t * 64;
        for (int idx = tid; idx < 64 * 64; idx += 256) {
            int kk = idx >> 6, ee = idx & 63;
            Vt[kk][ee] = g_V[(size_t)(b * LL + kb + kk) * DD + h * EE + ee];
        }
        for (int idx = tid; idx < UMAX * 64; idx += 256) {
            int q = idx >> 6, kk = idx & 63;
            St[q][kk] = (q < u) ? g_S[((size_t)bh * UMAX + q) * LL + kb + kk] : 0.f;
        }
        __syncthreads();
#pragma unroll 4
        for (int kk = 0; kk < 64; kk++) {
            float v = Vt[kk][e];
#pragma unroll
            for (int j = 0; j < 11; j++)
                acc[j] = fmaf(St[qs + 4 * j][kk], v, acc[j]);
        }
        __syncthreads();
    }
#pragma unroll
    for (int j = 0; j < 11; j++) {
        int q = qs + 4 * j;
        if (q < u)
            g_ctxP[(((size_t)split * NBH + bh) * UMAX + q) * EE + e] = acc[j];
    }
}

// ---------------- base row per batch ----------------
__global__ void __launch_bounds__(512)
base_kernel(const float* __restrict__ Wout, const float* __restrict__ bout)
{
    int b = blockIdx.x;
    int o = threadIdx.x;
    __shared__ float vm[DD];
    vm[o] = g_vsum[b * DD + o] * (1.f / (float)LL);
    __syncthreads();
    float acc = bout[o];
#pragma unroll 8
    for (int d = 0; d < DD; d++) acc = fmaf(vm[d], Wout[(size_t)d * DD + o], acc);
    g_base[b * DD + o] = acc;
}

// ---------------- broadcast base row ----------------
__global__ void fill_kernel(float* __restrict__ out)
{
    size_t idx = (size_t)blockIdx.x * 256 + threadIdx.x;
    int c = (int)(idx & 127);
    int r = (int)(idx >> 7);
    int b = r >> 12;
    ((float4*)out)[idx] = ((const float4*)(g_base + b * DD))[c];
}

// ---------------- rank-64 corrections (normalizes by rowsum) ----------------
__global__ void __launch_bounds__(128)
corr_kernel(float* __restrict__ out, const float* __restrict__ Wout)
{
    int qs = blockIdx.x;
    int bh = blockIdx.y;
    int b = bh >> 3, h = bh & 7;
    __shared__ float delta[EE];
    __shared__ int qidx_s;
    int tid = threadIdx.x;
    if (tid < EE) {
        float s = 0.f;
#pragma unroll
        for (int sp = 0; sp < NSPLIT; sp++)
            s += g_ctxP[(((size_t)sp * NBH + bh) * UMAX + qs) * EE + tid];
        float rinv = 1.f / g_rowsum[bh * UMAX + qs];
        delta[tid] = s * rinv - g_vsum[b * DD + h * EE + tid] * (1.f / (float)LL);
    }
    if (tid == 0) qidx_s = g_top[bh * UMAX + qs];
    __syncthreads();
    float* orow = out + (size_t)(b * LL + qidx_s) * DD;
    for (int o = tid; o < DD; o += 128) {
        float acc = 0.f;
#pragma unroll 8
        for (int e = 0; e < EE; e++)
            acc = fmaf(delta[e], Wout[(size_t)(h * EE + e) * DD + o], acc);
        atomicAdd(&orow[o], acc);
    }
}

// ---------------- launch ----------------
extern "C" void kernel_launch(void* const* d_in, const int* in_sizes, int n_in,
                              void* d_out, int out_size)
{
    const float* query  = (const float*)d_in[0];
    const float* key_in = (const float*)d_in[1];
    const float* value  = (const float*)d_in[2];
    const float* W_Q    = (const float*)d_in[3];
    const float* W_K    = (const float*)d_in[4];
    const float* W_V    = (const float*)d_in[5];
    const float* W_out  = (const float*)d_in[6];
    const float* b_out  = (const float*)d_in[7];
    const int*   sidx   = (const int*)d_in[8];
    float* out = (float*)d_out;

    int SK = in_sizes[8] / LL;
    int u = (int)(5.0 * log((double)LL + 1.0));
    if (u < 1) u = 1;
    if (u > UMAX) u = UMAX;

    float *pQ, *pK, *pV;
    cudaGetSymbolAddress((void**)&pQ, g_Q);
    cudaGetSymbolAddress((void**)&pK, g_K);
    cudaGetSymbolAddress((void**)&pV, g_V);

    cudaFuncSetAttribute(hmma_gemm_kernel, cudaFuncAttributeMaxDynamicSharedMemorySize, GEMM_SMEM);

    // mstage stays in the profiled slot (control measurement).
    splitA_kernel<<<dim3(16384, 3), 256>>>(query, key_in, value);      // 0
    splitW_kernel<<<dim3(16, 16, 3), dim3(32, 32)>>>(W_Q, W_K, W_V);   // 1
    hmma_gemm_kernel<<<dim3(4, 256, 3), 256, GEMM_SMEM>>>(pQ, pK, pV); // 2
    mstage_kernel<<<NROWS / 8, 256>>>(sidx, SK);                       // 3  <- profiled slot
    vsum_zero_kernel<<<BB * DD / 256, 256>>>();                        // 4
    vsum_kernel<<<dim3(2, 16, BB), 256>>>();                           // 5

    topk_kernel<<<NBH, 1024>>>(u);

    scores_kernel<<<dim3(LL / 128, NBH), 256>>>(u);   // exp + rowsum fused; softmax deleted
    ctx_kernel<<<dim3(NSPLIT, NBH), 256>>>(u);

    base_kernel<<<BB, 512>>>(W_out, b_out);
    fill_kernel<<<(size_t)BB * LL * DD / 4 / 256, 256>>>(out);
    corr_kernel<<<dim3(u, NBH), 128>>>(out, W_out);
}